// round 6
// baseline (speedup 1.0000x reference)
#include <cuda_runtime.h>
#include <math.h>

#define FULL_MASK 0xFFFFFFFFu

// RY on the qubit whose amplitude-index stride is STRIDE (qubit q -> 8>>q).
// new0 = c*a0 - s*a1 ; new1 = s*a0 + c*a1   (PennyLane real RY convention)
template<int STRIDE>
__device__ __forceinline__ void apply_ry_s(float st[16], float c, float s) {
#pragma unroll
    for (int base = 0; base < 16; base += 2 * STRIDE) {
#pragma unroll
        for (int i = 0; i < STRIDE; i++) {
            float a0 = st[base + i];
            float a1 = st[base + i + STRIDE];
            st[base + i]          = c * a0 - s * a1;
            st[base + i + STRIDE] = s * a0 + c * a1;
        }
    }
}

// CNOT(ctrl=0, tgt=1): where q0==1, swap q1 halves: idx 8..11 <-> 12..15
__device__ __forceinline__ void cnot01(float st[16]) {
#pragma unroll
    for (int i = 0; i < 4; i++) { float t = st[8 + i]; st[8 + i] = st[12 + i]; st[12 + i] = t; }
}
// CNOT(ctrl=2, tgt=3): where q2==1, swap q3: for b in {0,4,8,12}: st[b+2]<->st[b+3]
__device__ __forceinline__ void cnot23(float st[16]) {
#pragma unroll
    for (int b = 0; b < 16; b += 4) { float t = st[b + 2]; st[b + 2] = st[b + 3]; st[b + 3] = t; }
}
// CNOT(ctrl=1, tgt=2): where q1==1, swap q2: st[q0*8+4+q3] <-> st[q0*8+6+q3]
__device__ __forceinline__ void cnot12(float st[16]) {
#pragma unroll
    for (int q0 = 0; q0 < 2; q0++)
#pragma unroll
        for (int q3 = 0; q3 < 2; q3++) {
            int b = q0 * 8 + 4 + q3;
            float t = st[b]; st[b] = st[b + 2]; st[b + 2] = t;
        }
}

__global__ __launch_bounds__(256, 2)
void dqn_fused_kernel(const float* __restrict__ X,      // [B,512]
                      const float* __restrict__ Wpre,   // [4,512]
                      const float* __restrict__ bpre,   // [4]
                      const float* __restrict__ qp,     // [24]
                      const float* __restrict__ Wpost,  // [200,4]
                      const float* __restrict__ bpost,  // [200]
                      float* __restrict__ out,          // [B,200]
                      int B)
{
    // cos/sin of half layer-angles (shared across every sample) — once per block
    __shared__ float lc[24], ls[24];
    const int tid = threadIdx.x;
    if (tid < 24) {
        float s, c;
        sincosf(qp[tid] * 0.5f, &s, &c);
        lc[tid] = c; ls[tid] = s;
    }
    __syncthreads();

    const int lane = tid & 31;
    const int warp = tid >> 5;
    const int group = blockIdx.x * 8 + warp;   // one warp per 32 samples
    const int base = group * 32;
    if (base >= B) return;

    // ---- Phase 1: pre = X @ Wpre.T  (warp cooperates; lane ends up owning sample==lane)
    // W_pre in registers: lane covers columns {lane*4 + 128*j + 0..3}, j=0..3
    float4 w[4][4];
#pragma unroll
    for (int q = 0; q < 4; q++)
#pragma unroll
        for (int j = 0; j < 4; j++)
            w[q][j] = *(const float4*)(Wpre + q * 512 + j * 128 + lane * 4);

    float pre0 = 0.f, pre1 = 0.f, pre2 = 0.f, pre3 = 0.f;

#pragma unroll 4
    for (int s = 0; s < 32; s++) {
        const float* row = X + (size_t)(base + s) * 512 + lane * 4;
        float a0 = 0.f, a1 = 0.f, a2 = 0.f, a3 = 0.f;
#pragma unroll
        for (int j = 0; j < 4; j++) {
            float4 xv = *(const float4*)(row + j * 128);
            a0 += xv.x * w[0][j].x + xv.y * w[0][j].y + xv.z * w[0][j].z + xv.w * w[0][j].w;
            a1 += xv.x * w[1][j].x + xv.y * w[1][j].y + xv.z * w[1][j].z + xv.w * w[1][j].w;
            a2 += xv.x * w[2][j].x + xv.y * w[2][j].y + xv.z * w[2][j].z + xv.w * w[2][j].w;
            a3 += xv.x * w[3][j].x + xv.y * w[3][j].y + xv.z * w[3][j].z + xv.w * w[3][j].w;
        }
#pragma unroll
        for (int o = 16; o > 0; o >>= 1) {
            a0 += __shfl_xor_sync(FULL_MASK, a0, o);
            a1 += __shfl_xor_sync(FULL_MASK, a1, o);
            a2 += __shfl_xor_sync(FULL_MASK, a2, o);
            a3 += __shfl_xor_sync(FULL_MASK, a3, o);
        }
        if (lane == s) { pre0 = a0; pre1 = a1; pre2 = a2; pre3 = a3; }
    }

    // ---- Phase 2: per-lane (per-sample) 4-qubit circuit, 16 real amplitudes in regs
    float st[16];
#pragma unroll
    for (int i = 0; i < 16; i++) st[i] = 0.25f;

    {
        // q_in = tanh(pre + b) * pi/2 ; RY half-angle = q_in/2 = tanh(...)*pi/4
        const float PI_4 = 0.78539816339744830962f;
        float c, s, h;
        h = tanhf(pre0 + bpre[0]) * PI_4; sincosf(h, &s, &c); apply_ry_s<8>(st, c, s);
        h = tanhf(pre1 + bpre[1]) * PI_4; sincosf(h, &s, &c); apply_ry_s<4>(st, c, s);
        h = tanhf(pre2 + bpre[2]) * PI_4; sincosf(h, &s, &c); apply_ry_s<2>(st, c, s);
        h = tanhf(pre3 + bpre[3]) * PI_4; sincosf(h, &s, &c); apply_ry_s<1>(st, c, s);
    }

#pragma unroll
    for (int k = 0; k < 6; k++) {
        cnot01(st); cnot23(st); cnot12(st);
        apply_ry_s<8>(st, lc[k * 4 + 0], ls[k * 4 + 0]);
        apply_ry_s<4>(st, lc[k * 4 + 1], ls[k * 4 + 1]);
        apply_ry_s<2>(st, lc[k * 4 + 2], ls[k * 4 + 2]);
        apply_ry_s<1>(st, lc[k * 4 + 3], ls[k * 4 + 3]);
    }

    // Z expectations: z[q] = sum_{bit_q=0} p - sum_{bit_q=1} p  (q0 is bit 3 ... q3 is bit 0)
    float z0 = 0.f, z1 = 0.f, z2 = 0.f, z3 = 0.f;
#pragma unroll
    for (int i = 0; i < 16; i++) {
        float p = st[i] * st[i];
        z0 += (i & 8) ? -p : p;
        z1 += (i & 4) ? -p : p;
        z2 += (i & 2) ? -p : p;
        z3 += (i & 1) ? -p : p;
    }

    // ---- Phase 3: out[s][j] = z . Wpost[j] + bpost[j], coalesced float4 stores.
    // 200 cols = 128 (all lanes, j0=4*lane) + 72 (lanes 0..17, j1=128+4*lane)
    const int j0 = lane * 4;
    const int j1 = 128 + lane * 4;
    const bool second = (lane < 18);

    float4 wr0[4], wr1[4];
    float4 bp0 = *(const float4*)(bpost + j0);
    float4 bp1 = make_float4(0.f, 0.f, 0.f, 0.f);
#pragma unroll
    for (int r = 0; r < 4; r++) wr0[r] = *(const float4*)(Wpost + (j0 + r) * 4);
    if (second) {
#pragma unroll
        for (int r = 0; r < 4; r++) wr1[r] = *(const float4*)(Wpost + (j1 + r) * 4);
        bp1 = *(const float4*)(bpost + j1);
    } else {
#pragma unroll
        for (int r = 0; r < 4; r++) wr1[r] = make_float4(0.f, 0.f, 0.f, 0.f);
    }

#pragma unroll 4
    for (int s = 0; s < 32; s++) {
        float a0 = __shfl_sync(FULL_MASK, z0, s);
        float a1 = __shfl_sync(FULL_MASK, z1, s);
        float a2 = __shfl_sync(FULL_MASK, z2, s);
        float a3 = __shfl_sync(FULL_MASK, z3, s);
        float* orow = out + (size_t)(base + s) * 200;
        float4 o;
        o.x = bp0.x + a0 * wr0[0].x + a1 * wr0[0].y + a2 * wr0[0].z + a3 * wr0[0].w;
        o.y = bp0.y + a0 * wr0[1].x + a1 * wr0[1].y + a2 * wr0[1].z + a3 * wr0[1].w;
        o.z = bp0.z + a0 * wr0[2].x + a1 * wr0[2].y + a2 * wr0[2].z + a3 * wr0[2].w;
        o.w = bp0.w + a0 * wr0[3].x + a1 * wr0[3].y + a2 * wr0[3].z + a3 * wr0[3].w;
        *(float4*)(orow + j0) = o;
        if (second) {
            float4 p;
            p.x = bp1.x + a0 * wr1[0].x + a1 * wr1[0].y + a2 * wr1[0].z + a3 * wr1[0].w;
            p.y = bp1.y + a0 * wr1[1].x + a1 * wr1[1].y + a2 * wr1[1].z + a3 * wr1[1].w;
            p.z = bp1.z + a0 * wr1[2].x + a1 * wr1[2].y + a2 * wr1[2].z + a3 * wr1[2].w;
            p.w = bp1.w + a0 * wr1[3].x + a1 * wr1[3].y + a2 * wr1[3].z + a3 * wr1[3].w;
            *(float4*)(orow + j1) = p;
        }
    }
}

extern "C" void kernel_launch(void* const* d_in, const int* in_sizes, int n_in,
                              void* d_out, int out_size)
{
    const float* X     = (const float*)d_in[0];
    const float* Wpre  = (const float*)d_in[1];
    const float* bpre  = (const float*)d_in[2];
    const float* qp    = (const float*)d_in[3];
    const float* Wpost = (const float*)d_in[4];
    const float* bpost = (const float*)d_in[5];
    float* out = (float*)d_out;

    int B = in_sizes[0] / 512;            // 65536
    int groups = (B + 31) / 32;           // warps needed
    int blocks = (groups + 7) / 8;        // 8 warps (256 threads) per block

    dqn_fused_kernel<<<blocks, 256>>>(X, Wpre, bpre, qp, Wpost, bpost, out, B);
}